// round 2
// baseline (speedup 1.0000x reference)
#include <cuda_runtime.h>
#include <cstdint>
#include <cstdio>

#define NN 4
#define PP 128
#define HH 64
#define UU 64
#define BB 15
#define FAVG 49.0f

// ---------------- device scratch (no allocations allowed) ----------------
__device__ float g_rows[NN*HH*PP];     // sum_q xt[p,q] / npart        [n][h][p]
__device__ float g_cols[NN*HH*PP];     // sum_p xt[p,q] / npart        [n][h][q]
__device__ float g_diag[NN*HH*PP];     // xt[p,p]                      [n][h][p]
__device__ float g_sumdiag[NN*HH];     // sum_p diag / npart           [n][h]
__device__ float g_sumall[NN*HH];      // sum_pq xt / npart^2          [n][h]
__device__ float g_C0[HH*UU];          // coefs(h, b=0, u)
__device__ float g_C1[HH*UU];          // coefs(h, b=1, u)
__device__ float g_Fq[NN*PP*UU];       // q-field (includes bias)
__device__ float g_Fp[NN*PP*UU];       // p-field (includes constant field)
__device__ float g_Fd[NN*PP*UU];       // diagonal field (includes diag_bias)

// ---------------- pass 1: row/col/diag reductions ----------------
__global__ void reduce_kernel(const float* __restrict__ x,
                              const float* __restrict__ npart) {
    const int i = blockIdx.x;          // p (z=0) or q (z=1)
    const int n = blockIdx.y;
    const int t = threadIdx.x;
    const int h = t & 63;
    const int c = t >> 6;              // 0..3
    __shared__ float sp[4][64];
    const float inv = 1.0f / npart[n];

    if (blockIdx.z == 0) {
        // rowsum over q for fixed p=i, plus diagonal element
        const float* base = x + ((size_t)(n * PP + i)) * PP * HH;
        float s = 0.0f;
        #pragma unroll 4
        for (int q = c * 32; q < c * 32 + 32; ++q) s += base[q * HH + h];
        sp[c][h] = s;
        __syncthreads();
        if (c == 0) {
            float tot = sp[0][h] + sp[1][h] + sp[2][h] + sp[3][h];
            g_rows[(n * HH + h) * PP + i] = tot * inv;
            g_diag[(n * HH + h) * PP + i] = base[i * HH + h];
        }
    } else {
        // colsum over p for fixed q=i
        const float* base = x + ((size_t)n) * PP * PP * HH + i * HH;
        float s = 0.0f;
        #pragma unroll 4
        for (int p = c * 32; p < c * 32 + 32; ++p) s += base[(size_t)p * PP * HH + h];
        sp[c][h] = s;
        __syncthreads();
        if (c == 0) {
            g_cols[(n * HH + h) * PP + i] =
                (sp[0][h] + sp[1][h] + sp[2][h] + sp[3][h]) * inv;
        }
    }
}

// ---------------- pass 2: per-(n,h) scalars ----------------
__global__ void scalar_kernel(const float* __restrict__ npart) {
    const int n = blockIdx.x;
    const int h = threadIdx.x;
    const float inv = 1.0f / npart[n];
    float sd = 0.0f, sa = 0.0f;
    for (int p = 0; p < PP; ++p) {
        sd += g_diag[(n * HH + h) * PP + p];
        sa += g_rows[(n * HH + h) * PP + p];   // already /npart once
    }
    g_sumdiag[n * HH + h] = sd * inv;
    g_sumall[n * HH + h]  = sa * inv;          // total / npart^2
}

// ---------------- pass 3a: dense coefficient matrices (b=0,1 have alpha=0) ----------------
__global__ void cmat_kernel(const float* __restrict__ c00, const float* __restrict__ c01,
                            const float* __restrict__ c10, const float* __restrict__ c11) {
    const int h = blockIdx.x;
    const int u = threadIdx.x;
    const float r = c10[h * UU + u] * c11[h * UU + u];
    g_C0[h * UU + u] = c00[h * BB + 0] * c01[0 * UU + u] * r;
    g_C1[h * UU + u] = c00[h * BB + 1] * c01[1 * UU + u] * r;
}

// ---------------- pass 3b: folded low-rank fields Fq / Fp / Fd ----------------
__global__ void fvec_kernel(const float* __restrict__ npart,
                            const float* __restrict__ alpha0,
                            const float* __restrict__ c00,
                            const float* __restrict__ c01,
                            const float* __restrict__ c10,
                            const float* __restrict__ c11,
                            const float* __restrict__ bias,
                            const float* __restrict__ dbias) {
    const int i = blockIdx.x;   // spatial index (serves as both p and q role)
    const int n = blockIdx.y;
    const int u = threadIdx.x;  // 0..63

    __shared__ float s_mult[64][10];
    __shared__ float s_d[64], s_r[64], s_c[64], s_sd[64], s_sa[64];

    // thread u preloads the per-h scalars for h=u
    s_d[u]  = g_diag[(n * HH + u) * PP + i];
    s_r[u]  = g_rows[(n * HH + u) * PP + i];
    s_c[u]  = g_cols[(n * HH + u) * PP + i];
    s_sd[u] = g_sumdiag[n * HH + u];
    s_sa[u] = g_sumall[n * HH + u];
    const float ratio = npart[n] / FAVG;
    #pragma unroll
    for (int j = 0; j < 10; ++j)
        s_mult[u][j] = powf(ratio, alpha0[u * 10 + j]);  // h=u
    __syncthreads();

    float fq = bias[u];
    float fp = 0.0f;
    float fd = dbias[u];

    for (int h = 0; h < HH; ++h) {
        const float r = c10[h * UU + u] * c11[h * UU + u];
        const float* a00 = c00 + h * BB;
        const float* m = s_mult[h];
        const float d = s_d[h], rw = s_r[h], cl = s_c[h], sd = s_sd[h], sa = s_sa[h];

        const float c2  = a00[2]  * c01[2  * UU + u] * r;
        const float c3  = a00[3]  * c01[3  * UU + u] * r;
        const float c4  = a00[4]  * c01[4  * UU + u] * r;
        const float c5  = a00[5]  * c01[5  * UU + u] * r * m[0];
        const float c6  = a00[6]  * c01[6  * UU + u] * r * m[1];
        const float c7  = a00[7]  * c01[7  * UU + u] * r * m[2];
        const float c8  = a00[8]  * c01[8  * UU + u] * r * m[3];
        const float c9  = a00[9]  * c01[9  * UU + u] * r * m[4];
        const float c10v = a00[10] * c01[10 * UU + u] * r * m[5];
        const float c11v = a00[11] * c01[11 * UU + u] * r * m[6];
        const float c12v = a00[12] * c01[12 * UU + u] * r * m[7];
        const float c13v = a00[13] * c01[13 * UU + u] * r * m[8];
        const float c14v = a00[14] * c01[14 * UU + u] * r * m[9];

        fq += c2 * d + c5 * cl + c6 * rw;
        fp += c3 * d + c8 * cl + c9 * rw + c7 * sd + c13v * sa;
        fd += c4 * d + c10v * sd + c11v * rw + c12v * cl + c14v * sa;
    }
    g_Fq[(n * PP + i) * UU + u] = fq;
    g_Fp[(n * PP + i) * UU + u] = fp;
    g_Fd[(n * PP + i) * UU + u] = fd;
}

// ---------------- main: dual skinny GEMM (direct + transposed) + epilogue ----------------
#define XD_STRIDE 132  // 128 + 4 pad, keeps 16B alignment per k-row
constexpr int SMEM_FLOATS = 2 * 64 * XD_STRIDE + 2 * 64 * 64 + 128;

__global__ void __launch_bounds__(256, 2)
main_kernel(const float* __restrict__ x,
            const unsigned int* __restrict__ mask,   // 4-byte elements (bool -> int32/f32)
            float* __restrict__ out) {
    extern __shared__ float sm[];
    float* sXd = sm;                         // [k=64][q=128(+4)]  direct tile (k-major)
    float* sXt = sXd + 64 * XD_STRIDE;       // [k=64][q=128(+4)]  transposed tile
    float* sC0 = sXt + 64 * XD_STRIDE;       // [k=64][u=64]
    float* sC1 = sC0 + 64 * 64;              // [k=64][u=64]
    float* sFp = sC1 + 64 * 64;              // [64]
    float* sFd = sFp + 64;                   // [64]

    const int p = blockIdx.x;
    const int n = blockIdx.y;
    const int tid = threadIdx.x;

    // direct tile: x[n,p,q,h] -> sXd[h][q]   (one contiguous 32KB row-slab)
    const float4* xrow4 = (const float4*)(x + ((size_t)(n * PP + p)) * PP * HH);
    #pragma unroll
    for (int it = 0; it < 8; ++it) {
        const int idx4 = tid + it * 256;           // 0..2047, float4 over [q][h/4]
        const float4 v = xrow4[idx4];
        const int q  = idx4 >> 4;
        const int h0 = (idx4 & 15) << 2;
        sXd[(h0 + 0) * XD_STRIDE + q] = v.x;
        sXd[(h0 + 1) * XD_STRIDE + q] = v.y;
        sXd[(h0 + 2) * XD_STRIDE + q] = v.z;
        sXd[(h0 + 3) * XD_STRIDE + q] = v.w;
    }
    // transposed tile: x[n,r,p,h] -> sXt[h][r]  (128 rows of 256B, coalesced 16B/thread)
    {
        const int lane16 = tid & 15;
        const int h0 = lane16 << 2;
        #pragma unroll
        for (int it = 0; it < 8; ++it) {
            const int r = (tid >> 4) + it * 16;
            const float4 v = *(const float4*)(x + (((size_t)(n * PP + r)) * PP + p) * HH + h0);
            sXt[(h0 + 0) * XD_STRIDE + r] = v.x;
            sXt[(h0 + 1) * XD_STRIDE + r] = v.y;
            sXt[(h0 + 2) * XD_STRIDE + r] = v.z;
            sXt[(h0 + 3) * XD_STRIDE + r] = v.w;
        }
    }
    // coefficient matrices (L2-resident broadcast)
    {
        const float4* c04 = (const float4*)g_C0;
        const float4* c14 = (const float4*)g_C1;
        float4* d0 = (float4*)sC0;
        float4* d1 = (float4*)sC1;
        #pragma unroll
        for (int it = 0; it < 4; ++it) {
            const int i4 = tid + it * 256;   // 0..1023
            d0[i4] = c04[i4];
            d1[i4] = c14[i4];
        }
    }
    if (tid < 64) {
        sFp[tid] = g_Fp[(n * PP + p) * UU + tid];
        sFd[tid] = g_Fd[(n * PP + p) * UU + tid];
    }
    __syncthreads();

    // 16x16 thread grid; each thread: 8 q x 4 u micro-tile
    const int tx = tid & 15;
    const int ty = tid >> 4;
    const int u0 = tx << 2;
    const int q0 = ty << 3;

    float acc[8][4];
    #pragma unroll
    for (int i = 0; i < 8; ++i)
        #pragma unroll
        for (int j = 0; j < 4; ++j) acc[i][j] = 0.0f;

    #pragma unroll 8
    for (int k = 0; k < 64; ++k) {
        const float4 b0 = *(const float4*)(sC0 + k * 64 + u0);
        const float4 b1 = *(const float4*)(sC1 + k * 64 + u0);
        const float4 a0 = *(const float4*)(sXd + k * XD_STRIDE + q0);
        const float4 a1 = *(const float4*)(sXd + k * XD_STRIDE + q0 + 4);
        const float4 t0 = *(const float4*)(sXt + k * XD_STRIDE + q0);
        const float4 t1 = *(const float4*)(sXt + k * XD_STRIDE + q0 + 4);
        const float av[8] = {a0.x, a0.y, a0.z, a0.w, a1.x, a1.y, a1.z, a1.w};
        const float tv[8] = {t0.x, t0.y, t0.z, t0.w, t1.x, t1.y, t1.z, t1.w};
        const float bv0[4] = {b0.x, b0.y, b0.z, b0.w};
        const float bv1[4] = {b1.x, b1.y, b1.z, b1.w};
        #pragma unroll
        for (int i = 0; i < 8; ++i)
            #pragma unroll
            for (int j = 0; j < 4; ++j)
                acc[i][j] += av[i] * bv0[j] + tv[i] * bv1[j];
    }

    // epilogue: add low-rank fields, diagonal, mask, store
    const float4 fp4 = *(const float4*)(sFp + u0);
    const float4 fd4 = *(const float4*)(sFd + u0);
    const unsigned int* em = mask + (size_t)(n * PP + p) * PP;   // 4-byte mask elems
    #pragma unroll
    for (int i = 0; i < 8; ++i) {
        const int q = q0 + i;
        const float4 fq = *(const float4*)(g_Fq + ((size_t)(n * PP + q)) * UU + u0);
        const float msk = (em[q] != 0u) ? 1.0f : 0.0f;
        const float de = (q == p) ? 1.0f : 0.0f;
        float4 o;
        o.x = (acc[i][0] + fq.x + fp4.x + de * fd4.x) * msk;
        o.y = (acc[i][1] + fq.y + fp4.y + de * fd4.y) * msk;
        o.z = (acc[i][2] + fq.z + fp4.z + de * fd4.z) * msk;
        o.w = (acc[i][3] + fq.w + fp4.w + de * fd4.w) * msk;
        *(float4*)(out + (((size_t)(n * PP + p)) * PP + q) * UU + u0) = o;
    }
}

// ---------------- launch ----------------
extern "C" void kernel_launch(void* const* d_in, const int* in_sizes, int n_in,
                              void* d_out, int out_size) {
    (void)in_sizes; (void)n_in; (void)out_size;
    const float*        x      = (const float*)d_in[0];
    const unsigned int* mask   = (const unsigned int*)d_in[1];
    const float*        npart  = (const float*)d_in[2];
    const float*        alpha0 = (const float*)d_in[3];
    const float*        c00    = (const float*)d_in[4];
    const float*        c01    = (const float*)d_in[5];
    const float*        c10    = (const float*)d_in[6];
    const float*        c11    = (const float*)d_in[7];
    const float*        bias   = (const float*)d_in[8];
    const float*        dbias  = (const float*)d_in[9];
    float* out = (float*)d_out;

    reduce_kernel<<<dim3(PP, NN, 2), 256>>>(x, npart);
    scalar_kernel<<<NN, HH>>>(npart);
    cmat_kernel<<<HH, UU>>>(c00, c01, c10, c11);
    fvec_kernel<<<dim3(PP, NN), UU>>>(npart, alpha0, c00, c01, c10, c11, bias, dbias);

    cudaFuncSetAttribute(main_kernel, cudaFuncAttributeMaxDynamicSharedMemorySize,
                         SMEM_FLOATS * 4);
    main_kernel<<<dim3(PP, NN), 256, SMEM_FLOATS * 4>>>(x, mask, out);
}